// round 1
// baseline (speedup 1.0000x reference)
#include <cuda_runtime.h>
#include <math.h>

#define N_USERS 100000
#define N_ITEMS 50000
#define DD      64
#define NE      2000000
#define CAT_RATE 0.55f

// ------------------------- static device scratch (no allocs) -------------------------
__device__ float g_imgfeat[(size_t)N_ITEMS * DD];
__device__ float g_txtfeat[(size_t)N_ITEMS * DD];
__device__ float g_ug[(size_t)N_USERS * DD];
__device__ float g_uacc[(size_t)N_USERS * DD];
__device__ float g_ig[(size_t)N_ITEMS * DD];
__device__ float g_iacc[(size_t)N_ITEMS * DD];

__device__ int   g_ucnt[N_USERS];
__device__ int   g_icnt[N_ITEMS];
__device__ int   g_urp[N_USERS + 1];
__device__ int   g_irp[N_ITEMS + 1];
__device__ int   g_ucur[N_USERS];
__device__ int   g_icur[N_ITEMS];
__device__ int   g_ucol[NE];
__device__ float g_uval[NE];
__device__ int   g_icol[NE];
__device__ float g_ival[NE];
__device__ int   g_upart[128];
__device__ int   g_ipart[128];
__device__ float g_stats[66];   // [0..63] col sums -> means, [64] sum(x^2) -> inv rownorm

// ------------------------- CSR build -------------------------
__global__ void hist_kernel(const int* __restrict__ eu, const int* __restrict__ ei) {
    int i = blockIdx.x * blockDim.x + threadIdx.x;
    int stride = gridDim.x * blockDim.x;
    for (; i < NE; i += stride) {
        atomicAdd(&g_ucnt[eu[i]], 1);
        atomicAdd(&g_icnt[ei[i]], 1);
    }
}

// per-1024-chunk sums (blockDim=256, 4 elems/thread)
__global__ void block_sums(const int* __restrict__ cnt, int n, int* __restrict__ part) {
    __shared__ int sm[256];
    int t = threadIdx.x;
    int base = blockIdx.x * 1024;
    int s = 0;
    #pragma unroll
    for (int r = 0; r < 4; ++r) {
        int idx = base + t * 4 + r;
        if (idx < n) s += cnt[idx];
    }
    sm[t] = s; __syncthreads();
    for (int st = 128; st > 0; st >>= 1) { if (t < st) sm[t] += sm[t + st]; __syncthreads(); }
    if (t == 0) part[blockIdx.x] = sm[0];
}

// single-block exclusive scan of <=128 partials, in place
__global__ void scan_small(int* __restrict__ part, int n) {
    __shared__ int sm[128];
    int t = threadIdx.x;
    int v = (t < n) ? part[t] : 0;
    sm[t] = v; __syncthreads();
    for (int off = 1; off < 128; off <<= 1) {
        int x = (t >= off) ? sm[t - off] : 0;
        __syncthreads();
        sm[t] += x;
        __syncthreads();
    }
    part[t] = sm[t] - v;   // exclusive
}

// per-chunk scan + global offset -> exclusive row_ptr (+cursor copy)
__global__ void scan_chunks(const int* __restrict__ cnt, int n,
                            const int* __restrict__ part,
                            int* __restrict__ rp, int* __restrict__ cur) {
    __shared__ int sm[256];
    int t = threadIdx.x;
    int base = blockIdx.x * 1024;
    int v[4]; int local = 0;
    #pragma unroll
    for (int r = 0; r < 4; ++r) {
        int idx = base + t * 4 + r;
        v[r] = (idx < n) ? cnt[idx] : 0;
        local += v[r];
    }
    sm[t] = local; __syncthreads();
    for (int off = 1; off < 256; off <<= 1) {
        int x = (t >= off) ? sm[t - off] : 0;
        __syncthreads();
        sm[t] += x;
        __syncthreads();
    }
    int excl = sm[t] - local + part[blockIdx.x];
    #pragma unroll
    for (int r = 0; r < 4; ++r) {
        int idx = base + t * 4 + r;
        if (idx < n) { rp[idx] = excl; cur[idx] = excl; }
        excl += v[r];
    }
}

__global__ void set_tails() {
    g_urp[N_USERS] = NE;
    g_irp[N_ITEMS] = NE;
}

__global__ void scatter_kernel(const int* __restrict__ eu, const int* __restrict__ ei,
                               const float* __restrict__ vui, const float* __restrict__ viu) {
    int i = blockIdx.x * blockDim.x + threadIdx.x;
    int stride = gridDim.x * blockDim.x;
    for (; i < NE; i += stride) {
        int u = eu[i], it = ei[i];
        int p = atomicAdd(&g_ucur[u], 1);
        g_ucol[p] = it; g_uval[p] = vui[i];
        int q = atomicAdd(&g_icur[it], 1);
        g_icol[q] = u; g_ival[q] = viu[i];
    }
}

// ------------------------- dense GEMM: out[M,64] = A[M,K] @ W[K,64] + b -------------------------
// BM=64, BN=64, BK=32, 256 threads, 4x4 per thread
__global__ __launch_bounds__(256) void gemm64(const float* __restrict__ A,
                                              const float* __restrict__ W,
                                              const float* __restrict__ bias,
                                              float* __restrict__ out, int M, int K) {
    __shared__ float As[32][68];   // As[k][m], padded
    __shared__ float Ws[32][64];   // Ws[k][n]
    int tid = threadIdx.x;
    int tx = tid & 15;   // col group
    int ty = tid >> 4;   // row group
    int row0 = blockIdx.x * 64;
    float acc[4][4] = {};

    for (int k0 = 0; k0 < K; k0 += 32) {
        #pragma unroll
        for (int it = 0; it < 2; ++it) {
            int li = tid + it * 256;          // 0..511
            int lr = li >> 3;                 // row 0..63
            int lc = (li & 7) * 4;            // k col 0..28
            float4 a = make_float4(0.f, 0.f, 0.f, 0.f);
            if (row0 + lr < M)
                a = *(const float4*)(A + (size_t)(row0 + lr) * K + k0 + lc);
            As[lc + 0][lr] = a.x; As[lc + 1][lr] = a.y;
            As[lc + 2][lr] = a.z; As[lc + 3][lr] = a.w;
        }
        #pragma unroll
        for (int it = 0; it < 2; ++it) {
            int li = tid + it * 256;
            int lr = li >> 4;                 // k row 0..31
            int lc = (li & 15) * 4;           // n col
            *(float4*)&Ws[lr][lc] = *(const float4*)(W + (size_t)(k0 + lr) * 64 + lc);
        }
        __syncthreads();
        #pragma unroll
        for (int k = 0; k < 32; ++k) {
            float4 a4 = *(float4*)&As[k][ty * 4];
            float4 w4 = *(float4*)&Ws[k][tx * 4];
            acc[0][0] += a4.x * w4.x; acc[0][1] += a4.x * w4.y; acc[0][2] += a4.x * w4.z; acc[0][3] += a4.x * w4.w;
            acc[1][0] += a4.y * w4.x; acc[1][1] += a4.y * w4.y; acc[1][2] += a4.y * w4.z; acc[1][3] += a4.y * w4.w;
            acc[2][0] += a4.z * w4.x; acc[2][1] += a4.z * w4.y; acc[2][2] += a4.z * w4.z; acc[2][3] += a4.z * w4.w;
            acc[3][0] += a4.w * w4.x; acc[3][1] += a4.w * w4.y; acc[3][2] += a4.w * w4.z; acc[3][3] += a4.w * w4.w;
        }
        __syncthreads();
    }
    float4 b = *(const float4*)(bias + tx * 4);
    #pragma unroll
    for (int i = 0; i < 4; ++i) {
        int r = row0 + ty * 4 + i;
        if (r < M) {
            float4 o = make_float4(acc[i][0] + b.x, acc[i][1] + b.y,
                                   acc[i][2] + b.z, acc[i][3] + b.w);
            *(float4*)(out + (size_t)r * 64 + tx * 4) = o;
        }
    }
}

// ------------------------- SpMM (CSR, warp per dst row, lane = 2 cols) -------------------------
__global__ __launch_bounds__(256) void spmm_csr(const int* __restrict__ rp,
                                                const int* __restrict__ cols,
                                                const float* __restrict__ vals,
                                                const float* __restrict__ src,
                                                float* __restrict__ out,
                                                float* __restrict__ acc,
                                                int n_rows) {
    int row = blockIdx.x * (blockDim.x >> 5) + (threadIdx.x >> 5);
    if (row >= n_rows) return;
    int lane = threadIdx.x & 31;
    int s = rp[row], e = rp[row + 1];
    float ax = 0.f, ay = 0.f;
    for (int j = s; j < e; ++j) {
        float v = __ldg(&vals[j]);
        int c = __ldg(&cols[j]);
        float2 sv = *(const float2*)(src + (size_t)c * 64 + lane * 2);
        ax = fmaf(v, sv.x, ax);
        ay = fmaf(v, sv.y, ay);
    }
    size_t base = (size_t)row * 64 + lane * 2;
    *(float2*)(out + base) = make_float2(ax, ay);
    if (acc) {
        float2* ap = (float2*)(acc + base);
        float2 t = *ap;
        t.x += ax; t.y += ay;
        *ap = t;
    }
}

// ------------------------- normalization -------------------------
__global__ void norm_stats(const float* __restrict__ ue, const float* __restrict__ ie) {
    int t = threadIdx.x;           // 256
    int c = t & 63;
    int rsub = t >> 6;             // 0..3
    float s = 0.f, q = 0.f;
    for (int r = blockIdx.x * 4 + rsub; r < N_USERS + N_ITEMS; r += gridDim.x * 4) {
        const float* src = (r < N_USERS) ? (ue + (size_t)r * 64)
                                         : (ie + (size_t)(r - N_USERS) * 64);
        float v = src[c];
        s += v; q += v * v;
    }
    __shared__ float scol[256], sq[256];
    scol[t] = s; sq[t] = q;
    __syncthreads();
    for (int st = 128; st > 0; st >>= 1) { if (t < st) sq[t] += sq[t + st]; __syncthreads(); }
    if (t < 64) {
        float cs = scol[t] + scol[t + 64] + scol[t + 128] + scol[t + 192];
        atomicAdd(&g_stats[t], cs);
    }
    if (t == 0) atomicAdd(&g_stats[64], sq[0]);
}

__global__ void norm_finalize() {
    __shared__ float sm[64];
    int t = threadIdx.x;   // 64 threads
    float n = (float)(N_USERS + N_ITEMS);
    float mean = g_stats[t] / n;
    sm[t] = mean * mean;
    __syncthreads();
    for (int st = 32; st > 0; st >>= 1) { if (t < st) sm[t] += sm[t + st]; __syncthreads(); }
    g_stats[t] = mean;
    if (t == 0) {
        float Q = g_stats[64];
        float rn2 = Q / n - sm[0] + 1e-6f;
        g_stats[64] = rsqrtf(rn2);   // NORM_SCALE = 1
    }
}

__global__ void apply_norm(const float* __restrict__ emb, float* __restrict__ g,
                           float* __restrict__ acc, int ntot) {
    float inv = g_stats[64];
    int idx = blockIdx.x * blockDim.x + threadIdx.x;
    int stride = gridDim.x * blockDim.x;
    for (; idx < ntot; idx += stride) {
        int c = idx & 63;
        float v = (emb[idx] - g_stats[c]) * inv;
        g[idx] = v;
        acc[idx] = v;
    }
}

// ------------------------- final outputs -------------------------
__global__ __launch_bounds__(256) void finalize_out(const float* __restrict__ acc,
                                                    const float* __restrict__ A,
                                                    const float* __restrict__ B,
                                                    float* __restrict__ out, int n) {
    int row = blockIdx.x * (blockDim.x >> 5) + (threadIdx.x >> 5);
    if (row >= n) return;
    int lane = threadIdx.x & 31;
    size_t base = (size_t)row * 64 + lane * 2;
    float2 a = *(const float2*)(A + base);
    float2 b = *(const float2*)(B + base);
    float2 ac = *(const float2*)(acc + base);
    float sa = a.x * a.x + a.y * a.y;
    float sb = b.x * b.x + b.y * b.y;
    #pragma unroll
    for (int o = 16; o; o >>= 1) {
        sa += __shfl_xor_sync(0xFFFFFFFFu, sa, o);
        sb += __shfl_xor_sync(0xFFFFFFFFu, sb, o);
    }
    float ka = CAT_RATE / fmaxf(sqrtf(sa), 1e-12f);
    float kb = CAT_RATE / fmaxf(sqrtf(sb), 1e-12f);
    const float inv_layers = 1.0f / 3.0f;   // GNN_LAYERS + 1
    float2 o2 = make_float2(ac.x * inv_layers + ka * a.x + kb * b.x,
                            ac.y * inv_layers + ka * a.y + kb * b.y);
    *(float2*)(out + base) = o2;
}

// ------------------------- launch -------------------------
extern "C" void kernel_launch(void* const* d_in, const int* in_sizes, int n_in,
                              void* d_out, int out_size) {
    const float* image_feats = (const float*)d_in[0];
    const float* text_feats  = (const float*)d_in[1];
    const float* user_emb    = (const float*)d_in[2];
    const float* item_emb    = (const float*)d_in[3];
    const float* W_img       = (const float*)d_in[4];
    const float* b_img       = (const float*)d_in[5];
    const float* W_txt       = (const float*)d_in[6];
    const float* b_txt       = (const float*)d_in[7];
    const float* val_ui      = (const float*)d_in[8];
    const float* val_iu      = (const float*)d_in[9];
    const int*   edge_u      = (const int*)d_in[10];
    const int*   edge_i      = (const int*)d_in[11];

    float* out = (float*)d_out;
    float* o_u    = out;                    // 100000*64
    float* o_i    = out + 6400000;          // 50000*64
    float* o_imgI = out + 9600000;          // 50000*64
    float* o_txtI = out + 12800000;         // 50000*64
    float* o_imgU = out + 16000000;         // 100000*64
    float* o_txtU = out + 19200000 + 3200000; // = out + 22400000, 100000*64

    // scratch pointers
    void *p;
    float *imgfeat, *txtfeat, *ug, *uacc, *ig, *iacc, *stats, *uval, *ival;
    int *ucnt, *icnt, *urp, *irp, *ucur, *icur, *ucol, *icol, *upart, *ipart;
    cudaGetSymbolAddress(&p, g_imgfeat); imgfeat = (float*)p;
    cudaGetSymbolAddress(&p, g_txtfeat); txtfeat = (float*)p;
    cudaGetSymbolAddress(&p, g_ug);   ug   = (float*)p;
    cudaGetSymbolAddress(&p, g_uacc); uacc = (float*)p;
    cudaGetSymbolAddress(&p, g_ig);   ig   = (float*)p;
    cudaGetSymbolAddress(&p, g_iacc); iacc = (float*)p;
    cudaGetSymbolAddress(&p, g_ucnt); ucnt = (int*)p;
    cudaGetSymbolAddress(&p, g_icnt); icnt = (int*)p;
    cudaGetSymbolAddress(&p, g_urp);  urp  = (int*)p;
    cudaGetSymbolAddress(&p, g_irp);  irp  = (int*)p;
    cudaGetSymbolAddress(&p, g_ucur); ucur = (int*)p;
    cudaGetSymbolAddress(&p, g_icur); icur = (int*)p;
    cudaGetSymbolAddress(&p, g_ucol); ucol = (int*)p;
    cudaGetSymbolAddress(&p, g_icol); icol = (int*)p;
    cudaGetSymbolAddress(&p, g_uval); uval = (float*)p;
    cudaGetSymbolAddress(&p, g_ival); ival = (float*)p;
    cudaGetSymbolAddress(&p, g_upart); upart = (int*)p;
    cudaGetSymbolAddress(&p, g_ipart); ipart = (int*)p;
    cudaGetSymbolAddress(&p, g_stats); stats = (float*)p;

    // 0) zero counters + stats
    cudaMemsetAsync(ucnt, 0, N_USERS * sizeof(int));
    cudaMemsetAsync(icnt, 0, N_ITEMS * sizeof(int));
    cudaMemsetAsync(stats, 0, 66 * sizeof(float));

    // 1) CSR build (both directions)
    hist_kernel<<<2048, 256>>>(edge_u, edge_i);
    int nbu = (N_USERS + 1023) / 1024;   // 98
    int nbi = (N_ITEMS + 1023) / 1024;   // 49
    block_sums<<<nbu, 256>>>(ucnt, N_USERS, upart);
    block_sums<<<nbi, 256>>>(icnt, N_ITEMS, ipart);
    scan_small<<<1, 128>>>(upart, nbu);
    scan_small<<<1, 128>>>(ipart, nbi);
    scan_chunks<<<nbu, 256>>>(ucnt, N_USERS, upart, urp, ucur);
    scan_chunks<<<nbi, 256>>>(icnt, N_ITEMS, ipart, irp, icur);
    set_tails<<<1, 1>>>();
    scatter_kernel<<<2048, 256>>>(edge_u, edge_i, val_ui, val_iu);

    // 2) dense feature projections
    int gblocks = (N_ITEMS + 63) / 64;   // 782
    gemm64<<<gblocks, 256>>>(image_feats, W_img, b_img, imgfeat, N_ITEMS, 1024);
    gemm64<<<gblocks, 256>>>(text_feats,  W_txt, b_txt, txtfeat, N_ITEMS, 384);

    // 3) modality propagation (write directly to d_out regions)
    int sbu = (N_USERS + 7) / 8;   // 12500 blocks (8 warps/block)
    int sbi = (N_ITEMS + 7) / 8;   // 6250
    spmm_csr<<<sbu, 256>>>(urp, ucol, uval, imgfeat, o_imgU, nullptr, N_USERS);
    spmm_csr<<<sbi, 256>>>(irp, icol, ival, o_imgU,  o_imgI, nullptr, N_ITEMS);
    spmm_csr<<<sbu, 256>>>(urp, ucol, uval, txtfeat, o_txtU, nullptr, N_USERS);
    spmm_csr<<<sbi, 256>>>(irp, icol, ival, o_txtU,  o_txtI, nullptr, N_ITEMS);

    // 4) global normalization of [user_emb; item_emb]
    norm_stats<<<1024, 256>>>(user_emb, item_emb);
    norm_finalize<<<1, 64>>>();
    apply_norm<<<2048, 256>>>(user_emb, ug, uacc, N_USERS * 64);
    apply_norm<<<2048, 256>>>(item_emb, ig, iacc, N_ITEMS * 64);

    // 5) GNN layers (2x), with fused accumulation
    for (int l = 0; l < 2; ++l) {
        spmm_csr<<<sbu, 256>>>(urp, ucol, uval, ig, ug, uacc, N_USERS);
        spmm_csr<<<sbi, 256>>>(irp, icol, ival, ug, ig, iacc, N_ITEMS);
    }

    // 6) final outputs: acc/3 + 0.55*l2norm(img) + 0.55*l2norm(txt)
    finalize_out<<<sbu, 256>>>(uacc, o_imgU, o_txtU, o_u, N_USERS);
    finalize_out<<<sbi, 256>>>(iacc, o_imgI, o_txtI, o_i, N_ITEMS);
}

// round 5
// speedup vs baseline: 1.0454x; 1.0454x over previous
#include <cuda_runtime.h>
#include <math.h>

#define N_USERS 100000
#define N_ITEMS 50000
#define DD      64
#define NE      2000000
#define CAT_RATE 0.55f

#define NBU 98          // ceil(100000/1024)
#define NBI 49          // ceil(50000/1024)
#define GI  391         // ceil(50000/128) gemm blocks
#define SBU 12500       // 100000 rows / 8 warps
#define SBI 6250        // 50000 rows / 8 warps
#define SBU4 25000      // 100000 rows / 4 warps (128-thr phase)
#define APB 1024        // apply_norm grid-stride blocks

// ------------------------- static device scratch (no allocs) -------------------------
__device__ float g_imgfeat[(size_t)N_ITEMS * DD];
__device__ float g_txtfeat[(size_t)N_ITEMS * DD];
__device__ float g_ug[(size_t)N_USERS * DD];
__device__ float g_uacc[(size_t)N_USERS * DD];
__device__ float g_ig[(size_t)N_ITEMS * DD];
__device__ float g_iacc[(size_t)N_ITEMS * DD];

__device__ int   g_ucnt[N_USERS];
__device__ int   g_icnt[N_ITEMS];
__device__ int   g_urp[N_USERS + 1];
__device__ int   g_irp[N_ITEMS + 1];
__device__ int   g_ucur[N_USERS];
__device__ int   g_icur[N_ITEMS];
__device__ int   g_ucol[NE];
__device__ float g_uval[NE];
__device__ int   g_icol[NE];
__device__ float g_ival[NE];
__device__ int   g_upart[128];
__device__ int   g_ipart[128];
__device__ float g_stats[66];   // [0..63] col sums -> means, [64] inv rownorm

// ======================= device role functions =======================

__device__ __forceinline__ void dev_hist(const int* __restrict__ eu,
                                         const int* __restrict__ ei,
                                         int bid, int nb) {
    int i = bid * blockDim.x + threadIdx.x;
    int stride = nb * blockDim.x;
    for (; i < NE; i += stride) {
        atomicAdd(&g_ucnt[eu[i]], 1);
        atomicAdd(&g_icnt[ei[i]], 1);
    }
}

__device__ void dev_norm_stats(const float* __restrict__ ue,
                               const float* __restrict__ ie,
                               int bid, int nb) {
    int t = threadIdx.x;           // 256
    int c = t & 63;
    int rsub = t >> 6;             // 0..3
    float s = 0.f, q = 0.f;
    for (int r = bid * 4 + rsub; r < N_USERS + N_ITEMS; r += nb * 4) {
        const float* src = (r < N_USERS) ? (ue + (size_t)r * 64)
                                         : (ie + (size_t)(r - N_USERS) * 64);
        float v = src[c];
        s += v; q += v * v;
    }
    __shared__ float scol[256], sq[256];
    scol[t] = s; sq[t] = q;
    __syncthreads();
    for (int st = 128; st > 0; st >>= 1) { if (t < st) sq[t] += sq[t + st]; __syncthreads(); }
    if (t < 64) {
        float cs = scol[t] + scol[t + 64] + scol[t + 128] + scol[t + 192];
        atomicAdd(&g_stats[t], cs);
    }
    if (t == 0) atomicAdd(&g_stats[64], sq[0]);
}

__device__ void dev_block_sums(const int* __restrict__ cnt, int n,
                               int* __restrict__ part, int bid) {
    __shared__ int sm[256];
    int t = threadIdx.x;
    int base = bid * 1024;
    int s = 0;
    #pragma unroll
    for (int r = 0; r < 4; ++r) {
        int idx = base + t * 4 + r;
        if (idx < n) s += cnt[idx];
    }
    sm[t] = s; __syncthreads();
    for (int st = 128; st > 0; st >>= 1) { if (t < st) sm[t] += sm[t + st]; __syncthreads(); }
    if (t == 0) part[bid] = sm[0];
}

__device__ void dev_norm_finalize() {
    __shared__ float smf[64];
    int t = threadIdx.x;
    if (t < 64) {
        float n = (float)(N_USERS + N_ITEMS);
        float mean = g_stats[t] / n;
        smf[t] = mean * mean;
        __syncwarp(); // not enough: need 64-thread sync
    }
    __syncthreads();
    if (t < 64) {
        // serial-ish reduce by thread 0 over 64 entries (tiny, once)
        if (t == 0) {
            float ssum = 0.f;
            #pragma unroll
            for (int i = 0; i < 64; ++i) ssum += smf[i];
            float n = (float)(N_USERS + N_ITEMS);
            float Q = g_stats[64];
            float rn2 = Q / n - ssum + 1e-6f;
            smf[0] = rsqrtf(rn2);
        }
    }
    __syncthreads();
    if (t < 64) {
        float n = (float)(N_USERS + N_ITEMS);
        g_stats[t] = g_stats[t] / n;    // store means
    }
    __syncthreads();
    if (t == 0) g_stats[64] = smf[0];
}

__device__ void dev_scan_small(int* __restrict__ part, int n) {
    __shared__ int sm[128];
    int t = threadIdx.x;   // 128 threads
    int v = (t < n) ? part[t] : 0;
    sm[t] = v; __syncthreads();
    for (int off = 1; off < 128; off <<= 1) {
        int x = (t >= off) ? sm[t - off] : 0;
        __syncthreads();
        sm[t] += x;
        __syncthreads();
    }
    part[t] = sm[t] - v;   // exclusive
}

__device__ void dev_scan_chunks(const int* __restrict__ cnt, int n,
                                const int* __restrict__ part,
                                int* __restrict__ rp, int* __restrict__ cur, int bid) {
    __shared__ int sm[256];
    int t = threadIdx.x;
    int base = bid * 1024;
    int v[4]; int local = 0;
    #pragma unroll
    for (int r = 0; r < 4; ++r) {
        int idx = base + t * 4 + r;
        v[r] = (idx < n) ? cnt[idx] : 0;
        local += v[r];
    }
    sm[t] = local; __syncthreads();
    for (int off = 1; off < 256; off <<= 1) {
        int x = (t >= off) ? sm[t - off] : 0;
        __syncthreads();
        sm[t] += x;
        __syncthreads();
    }
    int excl = sm[t] - local + part[bid];
    #pragma unroll
    for (int r = 0; r < 4; ++r) {
        int idx = base + t * 4 + r;
        if (idx < n) { rp[idx] = excl; cur[idx] = excl; }
        excl += v[r];
    }
}

__device__ void dev_apply_norm(const float* __restrict__ ue,
                               const float* __restrict__ ie, int bid, int nb) {
    float inv = g_stats[64];
    int idx = bid * blockDim.x + threadIdx.x;
    int stride = nb * blockDim.x;
    const int NU = N_USERS * 64;
    const int NT = (N_USERS + N_ITEMS) * 64;
    for (; idx < NT; idx += stride) {
        int c = idx & 63;
        if (idx < NU) {
            float v = (ue[idx] - g_stats[c]) * inv;
            g_ug[idx] = v; g_uacc[idx] = v;
        } else {
            int j = idx - NU;
            float v = (ie[j] - g_stats[c]) * inv;
            g_ig[j] = v; g_iacc[j] = v;
        }
    }
}

__device__ void dev_scatter(const int* __restrict__ eu, const int* __restrict__ ei,
                            const float* __restrict__ vui, const float* __restrict__ viu,
                            int bid, int nb) {
    int i = bid * blockDim.x + threadIdx.x;
    int stride = nb * blockDim.x;
    for (; i < NE; i += stride) {
        int u = eu[i], it = ei[i];
        int p = atomicAdd(&g_ucur[u], 1);
        g_ucol[p] = it; g_uval[p] = vui[i];
        int q = atomicAdd(&g_icur[it], 1);
        g_icol[q] = u; g_ival[q] = viu[i];
    }
}

// dense GEMM: out[M,64] = A[M,K] @ W[K,64] + b. 128 threads, BM=128, 8x8 micro.
__device__ void dev_gemm128(const float* __restrict__ A,
                            const float* __restrict__ W,
                            const float* __restrict__ bias,
                            float* __restrict__ out, int M, int K, int bid) {
    __shared__ float As[16][132];
    __shared__ float Ws[16][64];
    int tid = threadIdx.x;
    int tx = tid & 7;
    int ty = tid >> 3;
    int row0 = bid * 128;
    int arow = row0 + tid;
    float acc[8][8] = {};

    int wr = tid >> 3;
    int wc = (tid & 7) * 8;

    for (int k0 = 0; k0 < K; k0 += 16) {
        float4 a0 = make_float4(0.f,0.f,0.f,0.f), a1 = a0, a2 = a0, a3 = a0;
        if (arow < M) {
            const float4* ap = (const float4*)(A + (size_t)arow * K + k0);
            a0 = ap[0]; a1 = ap[1]; a2 = ap[2]; a3 = ap[3];
        }
        As[ 0][tid] = a0.x; As[ 1][tid] = a0.y; As[ 2][tid] = a0.z; As[ 3][tid] = a0.w;
        As[ 4][tid] = a1.x; As[ 5][tid] = a1.y; As[ 6][tid] = a1.z; As[ 7][tid] = a1.w;
        As[ 8][tid] = a2.x; As[ 9][tid] = a2.y; As[10][tid] = a2.z; As[11][tid] = a2.w;
        As[12][tid] = a3.x; As[13][tid] = a3.y; As[14][tid] = a3.z; As[15][tid] = a3.w;
        const float4* wp = (const float4*)(W + (size_t)(k0 + wr) * 64 + wc);
        *(float4*)&Ws[wr][wc]     = wp[0];
        *(float4*)&Ws[wr][wc + 4] = wp[1];
        __syncthreads();
        #pragma unroll
        for (int k = 0; k < 16; ++k) {
            float am[8], wn[8];
            *(float4*)&am[0] = *(float4*)&As[k][ty * 8];
            *(float4*)&am[4] = *(float4*)&As[k][ty * 8 + 4];
            *(float4*)&wn[0] = *(float4*)&Ws[k][tx * 8];
            *(float4*)&wn[4] = *(float4*)&Ws[k][tx * 8 + 4];
            #pragma unroll
            for (int i = 0; i < 8; ++i)
                #pragma unroll
                for (int j = 0; j < 8; ++j)
                    acc[i][j] = fmaf(am[i], wn[j], acc[i][j]);
        }
        __syncthreads();
    }
    float4 b0 = *(const float4*)(bias + tx * 8);
    float4 b1 = *(const float4*)(bias + tx * 8 + 4);
    #pragma unroll
    for (int i = 0; i < 8; ++i) {
        int r = row0 + ty * 8 + i;
        if (r < M) {
            float4 o0 = make_float4(acc[i][0] + b0.x, acc[i][1] + b0.y,
                                    acc[i][2] + b0.z, acc[i][3] + b0.w);
            float4 o1 = make_float4(acc[i][4] + b1.x, acc[i][5] + b1.y,
                                    acc[i][6] + b1.z, acc[i][7] + b1.w);
            float4* op = (float4*)(out + (size_t)r * 64 + tx * 8);
            op[0] = o0; op[1] = o1;
        }
    }
}

// SpMM: warp per dst row, lane = 2 cols; optional accumulate
__device__ __forceinline__ void dev_spmm(const int* __restrict__ rp,
                                         const int* __restrict__ cols,
                                         const float* __restrict__ vals,
                                         const float* __restrict__ src,
                                         float* __restrict__ out,
                                         float* __restrict__ acc,
                                         int n_rows, int bid) {
    int row = bid * ((int)blockDim.x >> 5) + ((int)threadIdx.x >> 5);
    if (row >= n_rows) return;
    int lane = threadIdx.x & 31;
    int s = rp[row], e = rp[row + 1];
    float ax = 0.f, ay = 0.f;
    int j = s;
    for (; j + 2 <= e; j += 2) {
        float v0 = __ldg(&vals[j]);     int c0 = __ldg(&cols[j]);
        float v1 = __ldg(&vals[j + 1]); int c1 = __ldg(&cols[j + 1]);
        float2 s0 = *(const float2*)(src + (size_t)c0 * 64 + lane * 2);
        float2 s1 = *(const float2*)(src + (size_t)c1 * 64 + lane * 2);
        ax = fmaf(v0, s0.x, ax); ay = fmaf(v0, s0.y, ay);
        ax = fmaf(v1, s1.x, ax); ay = fmaf(v1, s1.y, ay);
    }
    if (j < e) {
        float v = __ldg(&vals[j]); int c = __ldg(&cols[j]);
        float2 sv = *(const float2*)(src + (size_t)c * 64 + lane * 2);
        ax = fmaf(v, sv.x, ax); ay = fmaf(v, sv.y, ay);
    }
    size_t base = (size_t)row * 64 + lane * 2;
    *(float2*)(out + base) = make_float2(ax, ay);
    if (acc) {
        float2* ap = (float2*)(acc + base);
        float2 t = *ap;
        t.x += ax; t.y += ay;
        *ap = t;
    }
}

__device__ __forceinline__ void dev_spmm_dual(const int* __restrict__ rp,
                                              const int* __restrict__ cols,
                                              const float* __restrict__ vals,
                                              const float* __restrict__ srcA,
                                              const float* __restrict__ srcB,
                                              float* __restrict__ outA,
                                              float* __restrict__ outB,
                                              int n_rows, int bid) {
    int row = bid * ((int)blockDim.x >> 5) + ((int)threadIdx.x >> 5);
    if (row >= n_rows) return;
    int lane = threadIdx.x & 31;
    int s = rp[row], e = rp[row + 1];
    float axA = 0.f, ayA = 0.f, axB = 0.f, ayB = 0.f;
    int j = s;
    for (; j + 2 <= e; j += 2) {
        float v0 = __ldg(&vals[j]);     int c0 = __ldg(&cols[j]);
        float v1 = __ldg(&vals[j + 1]); int c1 = __ldg(&cols[j + 1]);
        size_t o0 = (size_t)c0 * 64 + lane * 2;
        size_t o1 = (size_t)c1 * 64 + lane * 2;
        float2 a0 = *(const float2*)(srcA + o0);
        float2 b0 = *(const float2*)(srcB + o0);
        float2 a1 = *(const float2*)(srcA + o1);
        float2 b1 = *(const float2*)(srcB + o1);
        axA = fmaf(v0, a0.x, axA); ayA = fmaf(v0, a0.y, ayA);
        axB = fmaf(v0, b0.x, axB); ayB = fmaf(v0, b0.y, ayB);
        axA = fmaf(v1, a1.x, axA); ayA = fmaf(v1, a1.y, ayA);
        axB = fmaf(v1, b1.x, axB); ayB = fmaf(v1, b1.y, ayB);
    }
    if (j < e) {
        float v = __ldg(&vals[j]); int c = __ldg(&cols[j]);
        size_t o = (size_t)c * 64 + lane * 2;
        float2 a = *(const float2*)(srcA + o);
        float2 b = *(const float2*)(srcB + o);
        axA = fmaf(v, a.x, axA); ayA = fmaf(v, a.y, ayA);
        axB = fmaf(v, b.x, axB); ayB = fmaf(v, b.y, ayB);
    }
    size_t base = (size_t)row * 64 + lane * 2;
    *(float2*)(outA + base) = make_float2(axA, ayA);
    *(float2*)(outB + base) = make_float2(axB, ayB);
}

__device__ __forceinline__ void dev_finalize(const float* __restrict__ acc,
                                             const float* __restrict__ A,
                                             const float* __restrict__ B,
                                             float* __restrict__ out, int n, int bid) {
    int row = bid * ((int)blockDim.x >> 5) + ((int)threadIdx.x >> 5);
    if (row >= n) return;
    int lane = threadIdx.x & 31;
    size_t base = (size_t)row * 64 + lane * 2;
    float2 a = *(const float2*)(A + base);
    float2 b = *(const float2*)(B + base);
    float2 ac = *(const float2*)(acc + base);
    float sa = a.x * a.x + a.y * a.y;
    float sb = b.x * b.x + b.y * b.y;
    #pragma unroll
    for (int o = 16; o; o >>= 1) {
        sa += __shfl_xor_sync(0xFFFFFFFFu, sa, o);
        sb += __shfl_xor_sync(0xFFFFFFFFu, sb, o);
    }
    float ka = CAT_RATE / fmaxf(sqrtf(sa), 1e-12f);
    float kb = CAT_RATE / fmaxf(sqrtf(sb), 1e-12f);
    const float inv_layers = 1.0f / 3.0f;   // GNN_LAYERS + 1
    float2 o2 = make_float2(ac.x * inv_layers + ka * a.x + kb * b.x,
                            ac.y * inv_layers + ka * a.y + kb * b.y);
    *(float2*)(out + base) = o2;
}

// ======================= phase kernels (single stream, mega-launches) =======================

// A: histogram || norm_stats
__global__ __launch_bounds__(256) void phaseA(const int* __restrict__ eu,
                                              const int* __restrict__ ei,
                                              const float* __restrict__ ue,
                                              const float* __restrict__ ie) {
    int b = blockIdx.x;
    if (b < 2048) dev_hist(eu, ei, b, 2048);
    else          dev_norm_stats(ue, ie, b - 2048, 1024);
}

// B: block_sums u || block_sums i || norm_finalize
__global__ __launch_bounds__(256) void phaseB() {
    int b = blockIdx.x;
    if (b < NBU)            dev_block_sums(g_ucnt, N_USERS, g_upart, b);
    else if (b < NBU + NBI) dev_block_sums(g_icnt, N_ITEMS, g_ipart, b - NBU);
    else                    dev_norm_finalize();
}

// C: small scans + tails (2 blocks, 128 threads)
__global__ __launch_bounds__(128) void phaseC() {
    if (blockIdx.x == 0) {
        dev_scan_small(g_upart, NBU);
        if (threadIdx.x == 0) { g_urp[N_USERS] = NE; g_irp[N_ITEMS] = NE; }
    } else {
        dev_scan_small(g_ipart, NBI);
    }
}

// D: scan_chunks u/i || apply_norm
__global__ __launch_bounds__(256) void phaseD(const float* __restrict__ ue,
                                              const float* __restrict__ ie) {
    int b = blockIdx.x;
    if (b < NBU)            dev_scan_chunks(g_ucnt, N_USERS, g_upart, g_urp, g_ucur, b);
    else if (b < NBU + NBI) dev_scan_chunks(g_icnt, N_ITEMS, g_ipart, g_irp, g_icur, b - NBU);
    else                    dev_apply_norm(ue, ie, b - NBU - NBI, APB);
}

// E: scatter
__global__ __launch_bounds__(256) void phaseE(const int* __restrict__ eu,
                                              const int* __restrict__ ei,
                                              const float* __restrict__ vui,
                                              const float* __restrict__ viu) {
    dev_scatter(eu, ei, vui, viu, blockIdx.x, gridDim.x);
}

// F: gemm img || gemm txt || GNN layer-1 user spmm (128 threads)
__global__ __launch_bounds__(128) void phaseF(const float* __restrict__ imgF,
                                              const float* __restrict__ Wi,
                                              const float* __restrict__ bi,
                                              const float* __restrict__ txtF,
                                              const float* __restrict__ Wt,
                                              const float* __restrict__ bt) {
    int b = blockIdx.x;
    if (b < GI)            dev_gemm128(imgF, Wi, bi, g_imgfeat, N_ITEMS, 1024, b);
    else if (b < 2 * GI)   dev_gemm128(txtF, Wt, bt, g_txtfeat, N_ITEMS, 384, b - GI);
    else                   dev_spmm(g_urp, g_ucol, g_uval, g_ig, g_ug, g_uacc,
                                    N_USERS, b - 2 * GI);
}

// G: dual modality U || GNN layer-1 item spmm
__global__ __launch_bounds__(256) void phaseG(float* __restrict__ o_imgU,
                                              float* __restrict__ o_txtU) {
    int b = blockIdx.x;
    if (b < SBU) dev_spmm_dual(g_urp, g_ucol, g_uval, g_imgfeat, g_txtfeat,
                               o_imgU, o_txtU, N_USERS, b);
    else         dev_spmm(g_irp, g_icol, g_ival, g_ug, g_ig, g_iacc,
                          N_ITEMS, b - SBU);
}

// H: dual modality I || GNN layer-2 user spmm
__global__ __launch_bounds__(256) void phaseH(const float* __restrict__ o_imgU,
                                              const float* __restrict__ o_txtU,
                                              float* __restrict__ o_imgI,
                                              float* __restrict__ o_txtI) {
    int b = blockIdx.x;
    if (b < SBI) dev_spmm_dual(g_irp, g_icol, g_ival, o_imgU, o_txtU,
                               o_imgI, o_txtI, N_ITEMS, b);
    else         dev_spmm(g_urp, g_ucol, g_uval, g_ig, g_ug, g_uacc,
                          N_USERS, b - SBI);
}

// I: GNN layer-2 item spmm || finalize users
__global__ __launch_bounds__(256) void phaseI(const float* __restrict__ o_imgU,
                                              const float* __restrict__ o_txtU,
                                              float* __restrict__ o_u) {
    int b = blockIdx.x;
    if (b < SBI) dev_spmm(g_irp, g_icol, g_ival, g_ug, g_ig, g_iacc,
                          N_ITEMS, b);
    else         dev_finalize(g_uacc, o_imgU, o_txtU, o_u, N_USERS, b - SBI);
}

// J: finalize items
__global__ __launch_bounds__(256) void phaseJ(const float* __restrict__ o_imgI,
                                              const float* __restrict__ o_txtI,
                                              float* __restrict__ o_i) {
    dev_finalize(g_iacc, o_imgI, o_txtI, o_i, N_ITEMS, blockIdx.x);
}

// ======================= launch =======================
extern "C" void kernel_launch(void* const* d_in, const int* in_sizes, int n_in,
                              void* d_out, int out_size) {
    const float* image_feats = (const float*)d_in[0];
    const float* text_feats  = (const float*)d_in[1];
    const float* user_emb    = (const float*)d_in[2];
    const float* item_emb    = (const float*)d_in[3];
    const float* W_img       = (const float*)d_in[4];
    const float* b_img       = (const float*)d_in[5];
    const float* W_txt       = (const float*)d_in[6];
    const float* b_txt       = (const float*)d_in[7];
    const float* val_ui      = (const float*)d_in[8];
    const float* val_iu      = (const float*)d_in[9];
    const int*   edge_u      = (const int*)d_in[10];
    const int*   edge_i      = (const int*)d_in[11];

    float* out = (float*)d_out;
    float* o_u    = out;                      // 100000*64
    float* o_i    = out + 6400000;            // 50000*64
    float* o_imgI = out + 9600000;            // 50000*64
    float* o_txtI = out + 12800000;           // 50000*64
    float* o_imgU = out + 16000000;           // 100000*64
    float* o_txtU = out + 22400000;           // 100000*64

    void *p;
    int *ucnt, *icnt; float *stats;
    cudaGetSymbolAddress(&p, g_ucnt);  ucnt  = (int*)p;
    cudaGetSymbolAddress(&p, g_icnt);  icnt  = (int*)p;
    cudaGetSymbolAddress(&p, g_stats); stats = (float*)p;

    cudaMemsetAsync(ucnt, 0, N_USERS * sizeof(int));
    cudaMemsetAsync(icnt, 0, N_ITEMS * sizeof(int));
    cudaMemsetAsync(stats, 0, 66 * sizeof(float));

    phaseA<<<2048 + 1024, 256>>>(edge_u, edge_i, user_emb, item_emb);
    phaseB<<<NBU + NBI + 1, 256>>>();
    phaseC<<<2, 128>>>();
    phaseD<<<NBU + NBI + APB, 256>>>(user_emb, item_emb);
    phaseE<<<2048, 256>>>(edge_u, edge_i, val_ui, val_iu);
    phaseF<<<2 * GI + SBU4, 128>>>(image_feats, W_img, b_img,
                                   text_feats,  W_txt, b_txt);
    phaseG<<<SBU + SBI, 256>>>(o_imgU, o_txtU);
    phaseH<<<SBI + SBU, 256>>>(o_imgU, o_txtU, o_imgI, o_txtI);
    phaseI<<<SBI + SBU, 256>>>(o_imgU, o_txtU, o_u);
    phaseJ<<<SBI, 256>>>(o_imgI, o_txtI, o_i);
}

// round 6
// speedup vs baseline: 1.2786x; 1.2230x over previous
#include <cuda_runtime.h>
#include <math.h>
#include <stdint.h>

#define N_USERS 100000
#define N_ITEMS 50000
#define DD      64
#define NE      2000000
#define CAT_RATE 0.55f

#define NBU 98          // ceil(100000/1024)
#define NBI 49          // ceil(50000/1024)
#define GB  391         // ceil(50000/128) gemm blocks per matrix
#define SBU 12500       // 100000 rows / 8 warps
#define SBI 6250        // 50000 rows / 8 warps
#define APB 1024        // apply_norm grid-stride blocks
#define HB  2048        // hist blocks
#define NSB 1024        // norm_stats blocks

// ------------------------- static device scratch (no allocs) -------------------------
__device__ float g_imgfeat[(size_t)N_ITEMS * DD];
__device__ float g_txtfeat[(size_t)N_ITEMS * DD];
__device__ float g_ug[(size_t)N_USERS * DD];
__device__ float g_uacc[(size_t)N_USERS * DD];
__device__ float g_ig[(size_t)N_ITEMS * DD];
__device__ float g_iacc[(size_t)N_ITEMS * DD];

__device__ int   g_ucnt[N_USERS];
__device__ int   g_icnt[N_ITEMS];
__device__ int   g_urp[N_USERS + 1];
__device__ int   g_irp[N_ITEMS + 1];
__device__ int   g_ucur[N_USERS];
__device__ int   g_icur[N_ITEMS];
__device__ int   g_ucol[NE];
__device__ float g_uval[NE];
__device__ int   g_icol[NE];
__device__ float g_ival[NE];
__device__ int   g_upart[128];
__device__ int   g_ipart[128];
__device__ float g_stats[66];   // [0..63] col means, [64] inv rownorm

// ======================= device role functions =======================

__device__ __forceinline__ void dev_hist(const int* __restrict__ eu,
                                         const int* __restrict__ ei,
                                         int bid, int nb) {
    int i = bid * 256 + threadIdx.x;
    int stride = nb * 256;
    for (; i < NE; i += stride) {
        atomicAdd(&g_ucnt[eu[i]], 1);
        atomicAdd(&g_icnt[ei[i]], 1);
    }
}

__device__ void dev_norm_stats(const float* __restrict__ ue,
                               const float* __restrict__ ie,
                               int bid, int nb) {
    int t = threadIdx.x;           // 256
    int c = t & 63;
    int rsub = t >> 6;             // 0..3
    float s = 0.f, q = 0.f;
    for (int r = bid * 4 + rsub; r < N_USERS + N_ITEMS; r += nb * 4) {
        const float* src = (r < N_USERS) ? (ue + (size_t)r * 64)
                                         : (ie + (size_t)(r - N_USERS) * 64);
        float v = src[c];
        s += v; q += v * v;
    }
    __shared__ float scol[256], sq[256];
    scol[t] = s; sq[t] = q;
    __syncthreads();
    for (int st = 128; st > 0; st >>= 1) { if (t < st) sq[t] += sq[t + st]; __syncthreads(); }
    if (t < 64) {
        float cs = scol[t] + scol[t + 64] + scol[t + 128] + scol[t + 192];
        atomicAdd(&g_stats[t], cs);
    }
    if (t == 0) atomicAdd(&g_stats[64], sq[0]);
}

// ---------------- tf32 tensor-core GEMM: out[M,64] = A[M,K] @ W[K,64] + b -----------
// 256 threads = 8 warps; warp w owns rows [bid*128 + w*16, +16); BK = 64.
// A fragments loaded straight from GMEM (L1-cached, warp-exclusive rows).
// W staged in smem with permuted columns (n' = (n&7)*8 + (n>>3)) so the 8 B-frag
// values per k-step are contiguous (LDS.128).
__device__ __forceinline__ uint32_t f2tf32(float f) {
    uint32_t u;
    asm("cvt.rna.tf32.f32 %0, %1;" : "=r"(u) : "f"(f));
    return u;
}

#define WS_STRIDE 76    // floats per row (padded, float4-aligned, conflict-spread)

__device__ void dev_gemm_tf32(const float* __restrict__ A,
                              const float* __restrict__ W,
                              const float* __restrict__ bias,
                              float* __restrict__ out, int M, int K, int bid,
                              float* Ws /* [64*WS_STRIDE] smem */) {
    int tid  = threadIdx.x;
    int warp = tid >> 5, lane = tid & 31;
    int gid  = lane >> 2, tid4 = lane & 3;
    int rA = bid * 128 + warp * 16 + gid;        // row for a0/a2, c0/c1
    int rB = rA + 8;                             // row for a1/a3, c2/c3
    bool okA = rA < M, okB = rB < M;
    const float* ArA = A + (size_t)rA * K;
    const float* ArB = A + (size_t)rB * K;

    float c[8][4];
    #pragma unroll
    for (int t = 0; t < 8; ++t) { c[t][0]=0.f; c[t][1]=0.f; c[t][2]=0.f; c[t][3]=0.f; }

    for (int k0 = 0; k0 < K; k0 += 64) {
        // stage W[k0:k0+64][0:64] into permuted smem (tf32-converted)
        #pragma unroll
        for (int i = 0; i < 4; ++i) {
            int li = tid + i * 256;             // 0..1023 -> 64x64/4 float4 loads
            int r = li >> 4;                    // k row 0..63
            int cb = (li & 15) * 4;             // n col base
            float4 w = *(const float4*)(W + (size_t)(k0 + r) * 64 + cb);
            float* wr = Ws + r * WS_STRIDE;
            wr[((cb + 0) & 7) * 8 + ((cb + 0) >> 3)] = __uint_as_float(f2tf32(w.x));
            wr[((cb + 1) & 7) * 8 + ((cb + 1) >> 3)] = __uint_as_float(f2tf32(w.y));
            wr[((cb + 2) & 7) * 8 + ((cb + 2) >> 3)] = __uint_as_float(f2tf32(w.z));
            wr[((cb + 3) & 7) * 8 + ((cb + 3) >> 3)] = __uint_as_float(f2tf32(w.w));
        }
        __syncthreads();
        #pragma unroll
        for (int ks = 0; ks < 8; ++ks) {
            int kk = k0 + ks * 8;
            float a0 = 0.f, a1 = 0.f, a2 = 0.f, a3 = 0.f;
            if (okA) { a0 = ArA[kk + tid4]; a2 = ArA[kk + tid4 + 4]; }
            if (okB) { a1 = ArB[kk + tid4]; a3 = ArB[kk + tid4 + 4]; }
            uint32_t ua0 = f2tf32(a0), ua1 = f2tf32(a1);
            uint32_t ua2 = f2tf32(a2), ua3 = f2tf32(a3);
            const float* w0 = Ws + (ks * 8 + tid4) * WS_STRIDE + gid * 8;
            const float* w1 = Ws + (ks * 8 + tid4 + 4) * WS_STRIDE + gid * 8;
            float4 b0lo = *(const float4*)(w0);
            float4 b0hi = *(const float4*)(w0 + 4);
            float4 b1lo = *(const float4*)(w1);
            float4 b1hi = *(const float4*)(w1 + 4);
            const float* pb0 = (const float*)&b0lo;  // t=0..7 via lo/hi
            const float* pb1 = (const float*)&b1lo;
            float b0arr[8], b1arr[8];
            *(float4*)&b0arr[0] = b0lo; *(float4*)&b0arr[4] = b0hi;
            *(float4*)&b1arr[0] = b1lo; *(float4*)&b1arr[4] = b1hi;
            (void)pb0; (void)pb1;
            #pragma unroll
            for (int t = 0; t < 8; ++t) {
                uint32_t ub0 = __float_as_uint(b0arr[t]);
                uint32_t ub1 = __float_as_uint(b1arr[t]);
                asm volatile(
                    "mma.sync.aligned.m16n8k8.row.col.f32.tf32.tf32.f32 "
                    "{%0,%1,%2,%3}, {%4,%5,%6,%7}, {%8,%9}, {%0,%1,%2,%3};"
                    : "+f"(c[t][0]), "+f"(c[t][1]), "+f"(c[t][2]), "+f"(c[t][3])
                    : "r"(ua0), "r"(ua1), "r"(ua2), "r"(ua3), "r"(ub0), "r"(ub1));
            }
        }
        __syncthreads();
    }
    // epilogue: c[t][0..1] -> row rA cols t*8+2*tid4(+1); c[t][2..3] -> row rB
    #pragma unroll
    for (int t = 0; t < 8; ++t) {
        int n = t * 8 + 2 * tid4;
        float bx = bias[n], by = bias[n + 1];
        if (okA) *(float2*)(out + (size_t)rA * 64 + n) = make_float2(c[t][0] + bx, c[t][1] + by);
        if (okB) *(float2*)(out + (size_t)rB * 64 + n) = make_float2(c[t][2] + bx, c[t][3] + by);
    }
}

// ---------------- CSR scan helpers ----------------
__device__ void dev_block_sums(const int* __restrict__ cnt, int n,
                               int* __restrict__ part, int bid) {
    __shared__ int sm[256];
    int t = threadIdx.x;
    int base = bid * 1024;
    int s = 0;
    #pragma unroll
    for (int r = 0; r < 4; ++r) {
        int idx = base + t * 4 + r;
        if (idx < n) s += cnt[idx];
    }
    sm[t] = s; __syncthreads();
    for (int st = 128; st > 0; st >>= 1) { if (t < st) sm[t] += sm[t + st]; __syncthreads(); }
    if (t == 0) part[bid] = sm[0];
}

__device__ void dev_norm_finalize() {
    __shared__ float smf[64];
    int t = threadIdx.x;
    if (t < 64) {
        float n = (float)(N_USERS + N_ITEMS);
        float mean = g_stats[t] / n;
        smf[t] = mean * mean;
    }
    __syncthreads();
    if (t == 0) {
        float ssum = 0.f;
        #pragma unroll
        for (int i = 0; i < 64; ++i) ssum += smf[i];
        float n = (float)(N_USERS + N_ITEMS);
        float Q = g_stats[64];
        smf[0] = rsqrtf(Q / n - ssum + 1e-6f);
    }
    __syncthreads();
    if (t < 64) g_stats[t] = g_stats[t] / (float)(N_USERS + N_ITEMS);
    __syncthreads();
    if (t == 0) g_stats[64] = smf[0];
}

__device__ void dev_scan_small(int* __restrict__ part, int n) {
    __shared__ int sm[128];
    int t = threadIdx.x;   // 128 threads
    int v = (t < n) ? part[t] : 0;
    sm[t] = v; __syncthreads();
    for (int off = 1; off < 128; off <<= 1) {
        int x = (t >= off) ? sm[t - off] : 0;
        __syncthreads();
        sm[t] += x;
        __syncthreads();
    }
    part[t] = sm[t] - v;   // exclusive
}

__device__ void dev_scan_chunks(const int* __restrict__ cnt, int n,
                                const int* __restrict__ part,
                                int* __restrict__ rp, int* __restrict__ cur, int bid) {
    __shared__ int sm[256];
    int t = threadIdx.x;
    int base = bid * 1024;
    int v[4]; int local = 0;
    #pragma unroll
    for (int r = 0; r < 4; ++r) {
        int idx = base + t * 4 + r;
        v[r] = (idx < n) ? cnt[idx] : 0;
        local += v[r];
    }
    sm[t] = local; __syncthreads();
    for (int off = 1; off < 256; off <<= 1) {
        int x = (t >= off) ? sm[t - off] : 0;
        __syncthreads();
        sm[t] += x;
        __syncthreads();
    }
    int excl = sm[t] - local + part[bid];
    #pragma unroll
    for (int r = 0; r < 4; ++r) {
        int idx = base + t * 4 + r;
        if (idx < n) { rp[idx] = excl; cur[idx] = excl; }
        excl += v[r];
    }
}

__device__ void dev_apply_norm(const float* __restrict__ ue,
                               const float* __restrict__ ie, int bid, int nb) {
    float inv = g_stats[64];
    int idx = bid * 256 + threadIdx.x;
    int stride = nb * 256;
    const int NU = N_USERS * 64;
    const int NT = (N_USERS + N_ITEMS) * 64;
    for (; idx < NT; idx += stride) {
        int c = idx & 63;
        if (idx < NU) {
            float v = (ue[idx] - g_stats[c]) * inv;
            g_ug[idx] = v; g_uacc[idx] = v;
        } else {
            int j = idx - NU;
            float v = (ie[j] - g_stats[c]) * inv;
            g_ig[j] = v; g_iacc[j] = v;
        }
    }
}

__device__ void dev_scatter(const int* __restrict__ eu, const int* __restrict__ ei,
                            const float* __restrict__ vui, const float* __restrict__ viu,
                            int bid, int nb) {
    int i = bid * 256 + threadIdx.x;
    int stride = nb * 256;
    for (; i < NE; i += stride) {
        int u = eu[i], it = ei[i];
        int p = atomicAdd(&g_ucur[u], 1);
        g_ucol[p] = it; g_uval[p] = vui[i];
        int q = atomicAdd(&g_icur[it], 1);
        g_icol[q] = u; g_ival[q] = viu[i];
    }
}

// ---------------- SpMM variants (warp/row, lane = 2 cols) ----------------
__device__ __forceinline__ void dev_spmm(const int* __restrict__ rp,
                                         const int* __restrict__ cols,
                                         const float* __restrict__ vals,
                                         const float* __restrict__ src,
                                         float* __restrict__ out,
                                         float* __restrict__ acc,
                                         int n_rows, int bid) {
    int row = bid * 8 + ((int)threadIdx.x >> 5);
    if (row >= n_rows) return;
    int lane = threadIdx.x & 31;
    int s = rp[row], e = rp[row + 1];
    float ax = 0.f, ay = 0.f;
    int j = s;
    for (; j + 2 <= e; j += 2) {
        float v0 = __ldg(&vals[j]);     int c0 = __ldg(&cols[j]);
        float v1 = __ldg(&vals[j + 1]); int c1 = __ldg(&cols[j + 1]);
        float2 s0 = *(const float2*)(src + (size_t)c0 * 64 + lane * 2);
        float2 s1 = *(const float2*)(src + (size_t)c1 * 64 + lane * 2);
        ax = fmaf(v0, s0.x, ax); ay = fmaf(v0, s0.y, ay);
        ax = fmaf(v1, s1.x, ax); ay = fmaf(v1, s1.y, ay);
    }
    if (j < e) {
        float v = __ldg(&vals[j]); int c = __ldg(&cols[j]);
        float2 sv = *(const float2*)(src + (size_t)c * 64 + lane * 2);
        ax = fmaf(v, sv.x, ax); ay = fmaf(v, sv.y, ay);
    }
    size_t base = (size_t)row * 64 + lane * 2;
    *(float2*)(out + base) = make_float2(ax, ay);
    if (acc) {
        float2* ap = (float2*)(acc + base);
        float2 t = *ap;
        t.x += ax; t.y += ay;
        *ap = t;
    }
}

// triple-source: same CSR, three feature tables, acc on third output
__device__ __forceinline__ void dev_spmm3(const int* __restrict__ rp,
                                          const int* __restrict__ cols,
                                          const float* __restrict__ vals,
                                          const float* __restrict__ sA,
                                          const float* __restrict__ sB,
                                          const float* __restrict__ sC,
                                          float* __restrict__ oA,
                                          float* __restrict__ oB,
                                          float* __restrict__ oC,
                                          float* __restrict__ acc,
                                          int n_rows, int bid) {
    int row = bid * 8 + ((int)threadIdx.x >> 5);
    if (row >= n_rows) return;
    int lane = threadIdx.x & 31;
    int s = rp[row], e = rp[row + 1];
    float aAx=0.f, aAy=0.f, aBx=0.f, aBy=0.f, aCx=0.f, aCy=0.f;
    for (int j = s; j < e; ++j) {
        float v = __ldg(&vals[j]); int c = __ldg(&cols[j]);
        size_t o = (size_t)c * 64 + lane * 2;
        float2 a = *(const float2*)(sA + o);
        float2 b = *(const float2*)(sB + o);
        float2 d = *(const float2*)(sC + o);
        aAx = fmaf(v, a.x, aAx); aAy = fmaf(v, a.y, aAy);
        aBx = fmaf(v, b.x, aBx); aBy = fmaf(v, b.y, aBy);
        aCx = fmaf(v, d.x, aCx); aCy = fmaf(v, d.y, aCy);
    }
    size_t base = (size_t)row * 64 + lane * 2;
    *(float2*)(oA + base) = make_float2(aAx, aAy);
    *(float2*)(oB + base) = make_float2(aBx, aBy);
    *(float2*)(oC + base) = make_float2(aCx, aCy);
    float2* ap = (float2*)(acc + base);
    float2 t = *ap;
    t.x += aCx; t.y += aCy;
    *ap = t;
}

__device__ __forceinline__ void dev_finalize(const float* __restrict__ acc,
                                             const float* __restrict__ A,
                                             const float* __restrict__ B,
                                             float* __restrict__ out, int n, int bid) {
    int row = bid * 8 + ((int)threadIdx.x >> 5);
    if (row >= n) return;
    int lane = threadIdx.x & 31;
    size_t base = (size_t)row * 64 + lane * 2;
    float2 a = *(const float2*)(A + base);
    float2 b = *(const float2*)(B + base);
    float2 ac = *(const float2*)(acc + base);
    float sa = a.x * a.x + a.y * a.y;
    float sb = b.x * b.x + b.y * b.y;
    #pragma unroll
    for (int o = 16; o; o >>= 1) {
        sa += __shfl_xor_sync(0xFFFFFFFFu, sa, o);
        sb += __shfl_xor_sync(0xFFFFFFFFu, sb, o);
    }
    float ka = CAT_RATE / fmaxf(sqrtf(sa), 1e-12f);
    float kb = CAT_RATE / fmaxf(sqrtf(sb), 1e-12f);
    const float inv_layers = 1.0f / 3.0f;
    float2 o2 = make_float2(ac.x * inv_layers + ka * a.x + kb * b.x,
                            ac.y * inv_layers + ka * a.y + kb * b.y);
    *(float2*)(out + base) = o2;
}

// ======================= phase kernels =======================

// P1: gemm-img || gemm-txt || hist || norm_stats
__global__ __launch_bounds__(256) void phase1(const float* __restrict__ imgF,
                                              const float* __restrict__ Wi,
                                              const float* __restrict__ bi,
                                              const float* __restrict__ txtF,
                                              const float* __restrict__ Wt,
                                              const float* __restrict__ bt,
                                              const int* __restrict__ eu,
                                              const int* __restrict__ ei,
                                              const float* __restrict__ ue,
                                              const float* __restrict__ ie) {
    __shared__ float Ws[64 * WS_STRIDE];
    int b = blockIdx.x;
    if (b < GB)              dev_gemm_tf32(imgF, Wi, bi, g_imgfeat, N_ITEMS, 1024, b, Ws);
    else if (b < 2 * GB)     dev_gemm_tf32(txtF, Wt, bt, g_txtfeat, N_ITEMS, 384, b - GB, Ws);
    else if (b < 2 * GB + HB) dev_hist(eu, ei, b - 2 * GB, HB);
    else                     dev_norm_stats(ue, ie, b - 2 * GB - HB, NSB);
}

// P2: block_sums u || block_sums i || norm_finalize
__global__ __launch_bounds__(256) void phase2() {
    int b = blockIdx.x;
    if (b < NBU)            dev_block_sums(g_ucnt, N_USERS, g_upart, b);
    else if (b < NBU + NBI) dev_block_sums(g_icnt, N_ITEMS, g_ipart, b - NBU);
    else                    dev_norm_finalize();
}

// P3: small scans + tails
__global__ __launch_bounds__(128) void phase3() {
    if (blockIdx.x == 0) {
        dev_scan_small(g_upart, NBU);
        if (threadIdx.x == 0) { g_urp[N_USERS] = NE; g_irp[N_ITEMS] = NE; }
    } else {
        dev_scan_small(g_ipart, NBI);
    }
}

// P4: scan_chunks u/i || apply_norm
__global__ __launch_bounds__(256) void phase4(const float* __restrict__ ue,
                                              const float* __restrict__ ie) {
    int b = blockIdx.x;
    if (b < NBU)            dev_scan_chunks(g_ucnt, N_USERS, g_upart, g_urp, g_ucur, b);
    else if (b < NBU + NBI) dev_scan_chunks(g_icnt, N_ITEMS, g_ipart, g_irp, g_icur, b - NBU);
    else                    dev_apply_norm(ue, ie, b - NBU - NBI, APB);
}

// P5: scatter
__global__ __launch_bounds__(256) void phase5(const int* __restrict__ eu,
                                              const int* __restrict__ ei,
                                              const float* __restrict__ vui,
                                              const float* __restrict__ viu) {
    dev_scatter(eu, ei, vui, viu, blockIdx.x, gridDim.x);
}

// P6: triple-U: o_imgU, o_txtU, ug(layer1) + uacc
__global__ __launch_bounds__(256) void phase6(float* __restrict__ o_imgU,
                                              float* __restrict__ o_txtU) {
    dev_spmm3(g_urp, g_ucol, g_uval, g_imgfeat, g_txtfeat, g_ig,
              o_imgU, o_txtU, g_ug, g_uacc, N_USERS, blockIdx.x);
}

// P7: triple-I: o_imgI, o_txtI, ig(layer1) + iacc
__global__ __launch_bounds__(256) void phase7(const float* __restrict__ o_imgU,
                                              const float* __restrict__ o_txtU,
                                              float* __restrict__ o_imgI,
                                              float* __restrict__ o_txtI) {
    dev_spmm3(g_irp, g_icol, g_ival, o_imgU, o_txtU, g_ug,
              o_imgI, o_txtI, g_ig, g_iacc, N_ITEMS, blockIdx.x);
}

// P8: GNN layer-2 user spmm
__global__ __launch_bounds__(256) void phase8() {
    dev_spmm(g_urp, g_ucol, g_uval, g_ig, g_ug, g_uacc, N_USERS, blockIdx.x);
}

// P9: GNN layer-2 item spmm || finalize users
__global__ __launch_bounds__(256) void phase9(const float* __restrict__ o_imgU,
                                              const float* __restrict__ o_txtU,
                                              float* __restrict__ o_u) {
    int b = blockIdx.x;
    if (b < SBI) dev_spmm(g_irp, g_icol, g_ival, g_ug, g_ig, g_iacc, N_ITEMS, b);
    else         dev_finalize(g_uacc, o_imgU, o_txtU, o_u, N_USERS, b - SBI);
}

// P10: finalize items
__global__ __launch_bounds__(256) void phase10(const float* __restrict__ o_imgI,
                                               const float* __restrict__ o_txtI,
                                               float* __restrict__ o_i) {
    dev_finalize(g_iacc, o_imgI, o_txtI, o_i, N_ITEMS, blockIdx.x);
}

// ======================= launch =======================
extern "C" void kernel_launch(void* const* d_in, const int* in_sizes, int n_in,
                              void* d_out, int out_size) {
    const float* image_feats = (const float*)d_in[0];
    const float* text_feats  = (const float*)d_in[1];
    const float* user_emb    = (const float*)d_in[2];
    const float* item_emb    = (const float*)d_in[3];
    const float* W_img       = (const float*)d_in[4];
    const float* b_img       = (const float*)d_in[5];
    const float* W_txt       = (const float*)d_in[6];
    const float* b_txt       = (const float*)d_in[7];
    const float* val_ui      = (const float*)d_in[8];
    const float* val_iu      = (const float*)d_in[9];
    const int*   edge_u      = (const int*)d_in[10];
    const int*   edge_i      = (const int*)d_in[11];

    float* out = (float*)d_out;
    float* o_u    = out;                      // 100000*64
    float* o_i    = out + 6400000;            // 50000*64
    float* o_imgI = out + 9600000;            // 50000*64
    float* o_txtI = out + 12800000;           // 50000*64
    float* o_imgU = out + 16000000;           // 100000*64
    float* o_txtU = out + 22400000;           // 100000*64

    void *p;
    int *ucnt, *icnt; float *stats;
    cudaGetSymbolAddress(&p, g_ucnt);  ucnt  = (int*)p;
    cudaGetSymbolAddress(&p, g_icnt);  icnt  = (int*)p;
    cudaGetSymbolAddress(&p, g_stats); stats = (float*)p;

    cudaMemsetAsync(ucnt, 0, N_USERS * sizeof(int));
    cudaMemsetAsync(icnt, 0, N_ITEMS * sizeof(int));
    cudaMemsetAsync(stats, 0, 66 * sizeof(float));

    phase1<<<2 * GB + HB + NSB, 256>>>(image_feats, W_img, b_img,
                                       text_feats,  W_txt, b_txt,
                                       edge_u, edge_i, user_emb, item_emb);
    phase2<<<NBU + NBI + 1, 256>>>();
    phase3<<<2, 128>>>();
    phase4<<<NBU + NBI + APB, 256>>>(user_emb, item_emb);
    phase5<<<2048, 256>>>(edge_u, edge_i, val_ui, val_iu);
    phase6<<<SBU, 256>>>(o_imgU, o_txtU);
    phase7<<<SBI, 256>>>(o_imgU, o_txtU, o_imgI, o_txtI);
    phase8<<<SBU, 256>>>();
    phase9<<<SBI + SBU, 256>>>(o_imgU, o_txtU, o_u);
    phase10<<<SBI, 256>>>(o_imgI, o_txtI, o_i);
}